// round 3
// baseline (speedup 1.0000x reference)
#include <cuda_runtime.h>

// Problem constants
#define BSZ    16
#define MOUT   128
#define CBLK   8
#define NCH    1024
#define TLEN   2048
#define T4     (TLEN / 4)                 // 512 float4 per row
#define TOTAL4 (BSZ * MOUT * T4)          // 1,048,576 float4 outputs
#define GRID   1216                       // 152 SMs * 8 CTAs — one resident wave

// Persistent fused kernel.
//  Ax[b,m,t] = sum_c x[b, m*8+c, t] * tanh(blocks[m,c])
//  Flat grid-stride over all output float4s; m is warp-uniform so weights are
//  computed once per warp-iteration (1 tanh lane-parallel + 8 shuffles).
//  CTAs 0..127 additionally write A_full row m (block-diagonal of tanh).
__global__ void __launch_bounds__(256, 8)
fused_kernel(const float* __restrict__ x,
             const float* __restrict__ blocks,
             float* __restrict__ ax_out,
             float* __restrict__ afull_out)
{
    const int lane   = threadIdx.x & 31;
    const int stride = GRID * 256;
    const float4* __restrict__ x4 = reinterpret_cast<const float4*>(x);
    float4* __restrict__ o4       = reinterpret_cast<float4*>(ax_out);

    for (int idx = blockIdx.x * 256 + threadIdx.x; idx < TOTAL4; idx += stride) {
        const int t4 = idx & (T4 - 1);
        const int bm = idx >> 9;              // idx / 512  (warp-uniform)
        const int m  = bm & (MOUT - 1);

        // Weights for this row: lanes compute tanh in parallel, broadcast.
        const float wv = tanhf(__ldg(blocks + m * CBLK + (lane & 7)));
        const float w0 = __shfl_sync(0xffffffffu, wv, 0);
        const float w1 = __shfl_sync(0xffffffffu, wv, 1);
        const float w2 = __shfl_sync(0xffffffffu, wv, 2);
        const float w3 = __shfl_sync(0xffffffffu, wv, 3);
        const float w4 = __shfl_sync(0xffffffffu, wv, 4);
        const float w5 = __shfl_sync(0xffffffffu, wv, 5);
        const float w6 = __shfl_sync(0xffffffffu, wv, 6);
        const float w7 = __shfl_sync(0xffffffffu, wv, 7);

        const float4* __restrict__ xb = x4 + (size_t)bm * CBLK * T4;

        // Front-batch all 8 loads for MLP
        float4 v0 = xb[0 * T4 + t4];
        float4 v1 = xb[1 * T4 + t4];
        float4 v2 = xb[2 * T4 + t4];
        float4 v3 = xb[3 * T4 + t4];
        float4 v4 = xb[4 * T4 + t4];
        float4 v5 = xb[5 * T4 + t4];
        float4 v6 = xb[6 * T4 + t4];
        float4 v7 = xb[7 * T4 + t4];

        float4 acc;
        acc.x = v0.x * w0;  acc.y = v0.y * w0;  acc.z = v0.z * w0;  acc.w = v0.w * w0;
        acc.x += v1.x * w1; acc.y += v1.y * w1; acc.z += v1.z * w1; acc.w += v1.w * w1;
        acc.x += v2.x * w2; acc.y += v2.y * w2; acc.z += v2.z * w2; acc.w += v2.w * w2;
        acc.x += v3.x * w3; acc.y += v3.y * w3; acc.z += v3.z * w3; acc.w += v3.w * w3;
        acc.x += v4.x * w4; acc.y += v4.y * w4; acc.z += v4.z * w4; acc.w += v4.w * w4;
        acc.x += v5.x * w5; acc.y += v5.y * w5; acc.z += v5.z * w5; acc.w += v5.w * w5;
        acc.x += v6.x * w6; acc.y += v6.y * w6; acc.z += v6.z * w6; acc.w += v6.w * w6;
        acc.x += v7.x * w7; acc.y += v7.y * w7; acc.z += v7.z * w7; acc.w += v7.w * w7;

        o4[idx] = acc;
    }

    // A_full[m, j] = (j>>3 == m) ? tanh(blocks[j]) : 0 — CTAs 0..127, row per CTA.
    // 1024 floats per row = 256 float4; one per thread. Only the 2 threads whose
    // float4 lies on the diagonal block compute tanh.
    if (blockIdx.x < MOUT) {
        const int m  = blockIdx.x;
        const int j0 = threadIdx.x * 4;
        float4 a = make_float4(0.f, 0.f, 0.f, 0.f);
        if ((j0 >> 3) == m) {
            a.x = tanhf(__ldg(blocks + j0 + 0));
            a.y = tanhf(__ldg(blocks + j0 + 1));
            a.z = tanhf(__ldg(blocks + j0 + 2));
            a.w = tanhf(__ldg(blocks + j0 + 3));
        }
        reinterpret_cast<float4*>(afull_out + (size_t)m * NCH)[threadIdx.x] = a;
    }
}

extern "C" void kernel_launch(void* const* d_in, const int* in_sizes, int n_in,
                              void* d_out, int out_size)
{
    const float* x      = (const float*)d_in[0];
    const float* blocks = (const float*)d_in[1];
    float* out = (float*)d_out;

    // Output layout: Ax (B*M*T floats) followed by A_full (M*NCH floats)
    float* ax_out    = out;
    float* afull_out = out + (size_t)BSZ * MOUT * TLEN;

    fused_kernel<<<GRID, 256>>>(x, blocks, ax_out, afull_out);
}

// round 4
// speedup vs baseline: 1.0012x; 1.0012x over previous
#include <cuda_runtime.h>

// Problem constants
#define BSZ   16
#define MOUT  128
#define CBLK  8
#define NCH   1024
#define TLEN  2048
#define T4    (TLEN / 4)   // 512 float4 per row

// Fused kernel (R2 structure + streaming cache hints + 16-deep MLP):
//  Ax[b,m,t] = sum_c x[b, m*8+c, t] * tanh(blocks[m,c])
//  One CTA per (b,m): reads 8 contiguous rows of length T, writes 1 row.
//  All 16 float4 loads (2 t-positions x 8 rows) issued before any math.
//  CTAs with b==0 additionally write A_full row m.
__global__ void __launch_bounds__(256)
fused_kernel(const float* __restrict__ x,
             const float* __restrict__ blocks,
             float* __restrict__ ax_out,
             float* __restrict__ afull_out)
{
    const int bm = blockIdx.x;            // 0 .. BSZ*MOUT-1
    const int m  = bm & (MOUT - 1);
    const int b  = bm >> 7;               // bm / MOUT

    __shared__ float ws[CBLK];
    if (threadIdx.x < CBLK)
        ws[threadIdx.x] = tanhf(blocks[m * CBLK + threadIdx.x]);
    __syncthreads();

    const float w0 = ws[0], w1 = ws[1], w2 = ws[2], w3 = ws[3];
    const float w4 = ws[4], w5 = ws[5], w6 = ws[6], w7 = ws[7];

    const float4* __restrict__ xb =
        reinterpret_cast<const float4*>(x + ((size_t)b * NCH + (size_t)m * CBLK) * TLEN);
    float4* __restrict__ ob =
        reinterpret_cast<float4*>(ax_out + ((size_t)b * MOUT + m) * TLEN);

    const int tA = threadIdx.x;           // first t-position
    const int tB = threadIdx.x + 256;     // second t-position

    // ---- Front-batch ALL 16 streaming loads (evict-first, no L2 allocate) ----
    float4 a0 = __ldcs(xb + 0 * T4 + tA);
    float4 a1 = __ldcs(xb + 1 * T4 + tA);
    float4 a2 = __ldcs(xb + 2 * T4 + tA);
    float4 a3 = __ldcs(xb + 3 * T4 + tA);
    float4 a4 = __ldcs(xb + 4 * T4 + tA);
    float4 a5 = __ldcs(xb + 5 * T4 + tA);
    float4 a6 = __ldcs(xb + 6 * T4 + tA);
    float4 a7 = __ldcs(xb + 7 * T4 + tA);
    float4 b0 = __ldcs(xb + 0 * T4 + tB);
    float4 b1 = __ldcs(xb + 1 * T4 + tB);
    float4 b2 = __ldcs(xb + 2 * T4 + tB);
    float4 b3 = __ldcs(xb + 3 * T4 + tB);
    float4 b4 = __ldcs(xb + 4 * T4 + tB);
    float4 b5 = __ldcs(xb + 5 * T4 + tB);
    float4 b6 = __ldcs(xb + 6 * T4 + tB);
    float4 b7 = __ldcs(xb + 7 * T4 + tB);

    float4 accA;
    accA.x = a0.x * w0;  accA.y = a0.y * w0;  accA.z = a0.z * w0;  accA.w = a0.w * w0;
    accA.x += a1.x * w1; accA.y += a1.y * w1; accA.z += a1.z * w1; accA.w += a1.w * w1;
    accA.x += a2.x * w2; accA.y += a2.y * w2; accA.z += a2.z * w2; accA.w += a2.w * w2;
    accA.x += a3.x * w3; accA.y += a3.y * w3; accA.z += a3.z * w3; accA.w += a3.w * w3;
    accA.x += a4.x * w4; accA.y += a4.y * w4; accA.z += a4.z * w4; accA.w += a4.w * w4;
    accA.x += a5.x * w5; accA.y += a5.y * w5; accA.z += a5.z * w5; accA.w += a5.w * w5;
    accA.x += a6.x * w6; accA.y += a6.y * w6; accA.z += a6.z * w6; accA.w += a6.w * w6;
    accA.x += a7.x * w7; accA.y += a7.y * w7; accA.z += a7.z * w7; accA.w += a7.w * w7;
    __stcs(ob + tA, accA);

    float4 accB;
    accB.x = b0.x * w0;  accB.y = b0.y * w0;  accB.z = b0.z * w0;  accB.w = b0.w * w0;
    accB.x += b1.x * w1; accB.y += b1.y * w1; accB.z += b1.z * w1; accB.w += b1.w * w1;
    accB.x += b2.x * w2; accB.y += b2.y * w2; accB.z += b2.z * w2; accB.w += b2.w * w2;
    accB.x += b3.x * w3; accB.y += b3.y * w3; accB.z += b3.z * w3; accB.w += b3.w * w3;
    accB.x += b4.x * w4; accB.y += b4.y * w4; accB.z += b4.z * w4; accB.w += b4.w * w4;
    accB.x += b5.x * w5; accB.y += b5.y * w5; accB.z += b5.z * w5; accB.w += b5.w * w5;
    accB.x += b6.x * w6; accB.y += b6.y * w6; accB.z += b6.z * w6; accB.w += b6.w * w6;
    accB.x += b7.x * w7; accB.y += b7.y * w7; accB.z += b7.z * w7; accB.w += b7.w * w7;
    __stcs(ob + tB, accB);

    // A_full[m, j] = (j>>3 == m) ? tanh(blocks[j]) : 0 — written by the b==0 CTAs.
    if (b == 0) {
        const int j0 = threadIdx.x * 4;
        float4 a;
        a.x = ((j0 + 0) >> 3 == m) ? ws[(j0 + 0) & 7] : 0.0f;
        a.y = ((j0 + 1) >> 3 == m) ? ws[(j0 + 1) & 7] : 0.0f;
        a.z = ((j0 + 2) >> 3 == m) ? ws[(j0 + 2) & 7] : 0.0f;
        a.w = ((j0 + 3) >> 3 == m) ? ws[(j0 + 3) & 7] : 0.0f;
        reinterpret_cast<float4*>(afull_out + (size_t)m * NCH)[threadIdx.x] = a;
    }
}

extern "C" void kernel_launch(void* const* d_in, const int* in_sizes, int n_in,
                              void* d_out, int out_size)
{
    const float* x      = (const float*)d_in[0];
    const float* blocks = (const float*)d_in[1];
    float* out = (float*)d_out;

    // Output layout: Ax (B*M*T floats) followed by A_full (M*NCH floats)
    float* ax_out    = out;
    float* afull_out = out + (size_t)BSZ * MOUT * TLEN;

    fused_kernel<<<BSZ * MOUT, 256>>>(x, blocks, ax_out, afull_out);
}